// round 6
// baseline (speedup 1.0000x reference)
#include <cuda_runtime.h>
#include <cuda_bf16.h>
#include <cmath>

#define T_  200
#define B_  256
#define M_  (T_ * B_)      // 51200 rows

__device__ float g_xproj[M_ * 200];  // [T,B,4H] flat row r = t*256+b
__device__ float g_hs[M_ * 50];      // [T,B,H]

// ---------------- f32x2 packed fp32 helpers ----------------
__device__ __forceinline__ unsigned long long fma2(unsigned long long a,
                                                   unsigned long long b,
                                                   unsigned long long c) {
    unsigned long long d;
    asm("fma.rn.f32x2 %0, %1, %2, %3;" : "=l"(d) : "l"(a), "l"(b), "l"(c));
    return d;
}
__device__ __forceinline__ unsigned long long add2(unsigned long long a,
                                                   unsigned long long b) {
    unsigned long long d;
    asm("add.rn.f32x2 %0, %1, %2;" : "=l"(d) : "l"(a), "l"(b));
    return d;
}
__device__ __forceinline__ float2 u2f(unsigned long long v) {
    float2 r;
    asm("mov.b64 {%0, %1}, %2;" : "=f"(r.x), "=f"(r.y) : "l"(v));
    return r;
}
__device__ __forceinline__ unsigned smem_u32(const void* p) {
    return (unsigned)__cvta_generic_to_shared(p);
}
__device__ __forceinline__ void cp16(unsigned dst, const void* src) {
    asm volatile("cp.async.cg.shared.global [%0], [%1], 16;" :: "r"(dst), "l"(src));
}
__device__ __forceinline__ float frcp(float x) {
    float r; asm("rcp.approx.f32 %0, %1;" : "=f"(r) : "f"(x)); return r;
}
__device__ __forceinline__ float sigm(float x) {
    return frcp(1.f + __expf(-x));
}
__device__ __forceinline__ float tanh_fast(float x) {
    return fmaf(2.f, sigm(2.f * x), -1.f);
}

// ---------------------------------------------------------------------------
// K1: x_proj = gather(emb, tokens) @ Wih^T + (bih+bhh)   (unchanged)
// ---------------------------------------------------------------------------
#define K1_ASZ  8192
#define K1_BSZ  25600
#define K1_SMEM_WORDS (K1_BSZ + 2*K1_ASZ + 200)

__global__ __launch_bounds__(512, 1) void k1_xproj(
    const int*   __restrict__ tokens,
    const float* __restrict__ emb,
    const float* __restrict__ Wih,
    const float* __restrict__ bih,
    const float* __restrict__ bhh)
{
    extern __shared__ __align__(16) float sm[];
    float* Bs   = sm;
    float* As   = sm + K1_BSZ;
    float* bsum = sm + K1_BSZ + 2*K1_ASZ;

    const int tid  = threadIdx.x;
    const int lane = tid & 31;
    const int warp = tid >> 5;
    const int cgB  = (warp >= 8);
    const int rg   = warp & 7;

    for (int i = tid; i < K1_BSZ; i += 512) {
        const int n = i >> 7;
        const int k = i & 127;
        Bs[(k >> 1) * 400 + 2 * n + (k & 1)] = Wih[i];
    }
    if (tid < 200) bsum[tid] = bih[tid] + bhh[tid];

    const int cta   = blockIdx.x;
    const int nblk  = (cta < 60) ? 6 : 5;
    const int start = cta * 5 + ((cta < 60) ? cta : 60);

    {
        const int row0 = start * 64;
        for (int i = tid; i < 2048; i += 512) {
            const int m  = i >> 5;
            const int ch = i & 31;
            cp16(smem_u32(&As[m * 128 + ch * 4]),
                 emb + (size_t)tokens[row0 + m] * 128 + ch * 4);
        }
        asm volatile("cp.async.commit_group;");
    }

    for (int blk = 0; blk < nblk; blk++) {
        asm volatile("cp.async.wait_group 0;");
        __syncthreads();

        if (blk + 1 < nblk) {
            const int row0 = (start + blk + 1) * 64;
            float* dst = As + ((blk + 1) & 1) * K1_ASZ;
            for (int i = tid; i < 2048; i += 512) {
                const int m  = i >> 5;
                const int ch = i & 31;
                cp16(smem_u32(&dst[m * 128 + ch * 4]),
                     emb + (size_t)tokens[row0 + m] * 128 + ch * 4);
            }
            asm volatile("cp.async.commit_group;");
        }

        const float* Ab = As + (blk & 1) * K1_ASZ + rg * 8 * 128;
        const int wbase = cgB ? (256 + 4 * lane) : (8 * lane);

        unsigned long long acc[8][4];
#pragma unroll
        for (int m = 0; m < 8; m++)
#pragma unroll
            for (int j = 0; j < 4; j++) acc[m][j] = 0ull;

#pragma unroll 2
        for (int kk4 = 0; kk4 < 32; kk4++) {
            const float* brow = &Bs[kk4 * 800];
            ulonglong2 p0, p1, p2, p3;
            if (!cgB) {
                p0 = *reinterpret_cast<const ulonglong2*>(brow + wbase);
                p1 = *reinterpret_cast<const ulonglong2*>(brow + wbase + 4);
                p2 = *reinterpret_cast<const ulonglong2*>(brow + wbase + 400);
                p3 = *reinterpret_cast<const ulonglong2*>(brow + wbase + 404);
            } else {
                p0 = *reinterpret_cast<const ulonglong2*>(brow + wbase);
                p2 = *reinterpret_cast<const ulonglong2*>(brow + wbase + 400);
                if (lane < 4) {
                    p1 = *reinterpret_cast<const ulonglong2*>(brow + 384 + 4*lane);
                    p3 = *reinterpret_cast<const ulonglong2*>(brow + 784 + 4*lane);
                } else { p1 = make_ulonglong2(0,0); p3 = make_ulonglong2(0,0); }
            }
#pragma unroll
            for (int m = 0; m < 8; m++) {
                const ulonglong2 av = *reinterpret_cast<const ulonglong2*>(
                    &Ab[m * 128 + kk4 * 4]);
                acc[m][0] = fma2(av.x, p0.x, acc[m][0]);
                acc[m][1] = fma2(av.x, p0.y, acc[m][1]);
                acc[m][2] = fma2(av.x, p1.x, acc[m][2]);
                acc[m][3] = fma2(av.x, p1.y, acc[m][3]);
                acc[m][0] = fma2(av.y, p2.x, acc[m][0]);
                acc[m][1] = fma2(av.y, p2.y, acc[m][1]);
                acc[m][2] = fma2(av.y, p3.x, acc[m][2]);
                acc[m][3] = fma2(av.y, p3.y, acc[m][3]);
            }
        }

        const int r0 = (start + blk) * 64 + rg * 8;
        if (!cgB) {
            const float4 bq = *reinterpret_cast<const float4*>(&bsum[4 * lane]);
#pragma unroll
            for (int m = 0; m < 8; m++) {
                const float2 s0 = u2f(acc[m][0]), s1 = u2f(acc[m][1]);
                const float2 s2 = u2f(acc[m][2]), s3 = u2f(acc[m][3]);
                float4 o;
                o.x = s0.x + s0.y + bq.x;
                o.y = s1.x + s1.y + bq.y;
                o.z = s2.x + s2.y + bq.z;
                o.w = s3.x + s3.y + bq.w;
                *reinterpret_cast<float4*>(
                    &g_xproj[(size_t)(r0 + m) * 200 + 4 * lane]) = o;
            }
        } else {
#pragma unroll
            for (int m = 0; m < 8; m++) {
                const float2 s0 = u2f(acc[m][0]), s1 = u2f(acc[m][1]);
                float2 o;
                o.x = s0.x + s0.y + bsum[128 + 2 * lane];
                o.y = s1.x + s1.y + bsum[129 + 2 * lane];
                *reinterpret_cast<float2*>(
                    &g_xproj[(size_t)(r0 + m) * 200 + 128 + 2 * lane]) = o;
                if (lane < 4) {
                    const float2 s2 = u2f(acc[m][2]), s3 = u2f(acc[m][3]);
                    float2 o2;
                    o2.x = s2.x + s2.y + bsum[192 + 2 * lane];
                    o2.y = s3.x + s3.y + bsum[193 + 2 * lane];
                    *reinterpret_cast<float2*>(
                        &g_xproj[(size_t)(r0 + m) * 200 + 192 + 2 * lane]) = o2;
                }
            }
        }
        __syncthreads();
    }
}

// ---------------------------------------------------------------------------
// K2: LSTM recurrence, ONE barrier per step.
// 128 CTAs x 512 threads, 2 groups of 256; group g owns batch b = blk*2+g.
// Gate threads j in [0,100): unit u = j>>1, half p = j&1.
//   p=0 computes dots for gates i(u), g(u);  p=1 computes f(u), o(u).
//   Activation is thread-local; si*tg crosses p=0 -> p=1 via one shfl_xor.
//   h double-buffered (read buf t&1, write buf (t&1)^1) -> single bar/step.
// Loader threads j in [128,178) stage x_proj via 8-deep cp.async ring.
// Gate warps = warps 0-3 (g0) / 8-11 (g1): exactly one per SMSP per group.
// ---------------------------------------------------------------------------
#define S_ 8

__global__ __launch_bounds__(512, 1) void k2_lstm(const float* __restrict__ Whh)
{
    __shared__ __align__(16) float h_s[2][2][52];   // [group][buf][unit]
    __shared__ __align__(16) float xs[2][S_][200];

    const int tid = threadIdx.x;
    const int g   = tid >> 8;
    const int j   = tid & 255;
    const int b   = blockIdx.x * 2 + g;

    const bool gatep  = (j < 100);
    const int  u      = j >> 1;
    const int  p      = j & 1;
    const bool loader = (j >= 128 && j < 178);
    const int  lj     = j - 128;

    // rows: p=0 -> i(u), g(u);  p=1 -> f(u), o(u)
    const int row0 = u + p * 50;
    const int row1 = u + 100 + p * 50;

    unsigned long long w0[25], w1[25];
    if (gatep) {
        const float2* wr0 = reinterpret_cast<const float2*>(Whh + row0 * 50);
        const float2* wr1 = reinterpret_cast<const float2*>(Whh + row1 * 50);
#pragma unroll
        for (int q = 0; q < 25; q++) {
            w0[q] = *reinterpret_cast<const unsigned long long*>(&wr0[q]);
            w1[q] = *reinterpret_cast<const unsigned long long*>(&wr1[q]);
        }
    }
    if (j < 52) { h_s[g][0][j] = 0.f; h_s[g][1][j] = 0.f; }

    // Prologue: stage x_proj for steps 0..S_-2
    if (loader) {
#pragma unroll
        for (int s = 0; s < S_ - 1; s++) {
            cp16(smem_u32(&xs[g][s][lj * 4]),
                 g_xproj + ((size_t)(s * B_ + b) * 200) + lj * 4);
            asm volatile("cp.async.commit_group;");
        }
        asm volatile("cp.async.wait_group %0;" :: "n"(S_ - 3));
    }
    __syncthreads();

    float c = 0.f;   // lives in p==1 threads

    for (int t = 0; t < T_; t++) {
        const int slot = t & (S_ - 1);
        const int buf  = t & 1;

        if (loader) {
            const int ts = t + S_ - 1;
            if (ts < T_)
                cp16(smem_u32(&xs[g][ts & (S_ - 1)][lj * 4]),
                     g_xproj + ((size_t)(ts * B_ + b) * 200) + lj * 4);
            asm volatile("cp.async.commit_group;");
        }

        if (j < 128) {   // warps 0-3 of the group: all execute the shfl
            float d0 = 0.f, d1 = 0.f;
            if (gatep) {
                const float xp0 = xs[g][slot][row0];
                const float xp1 = xs[g][slot][row1];
                const unsigned long long* h2 =
                    reinterpret_cast<const unsigned long long*>(h_s[g][buf]);
                unsigned long long a0 = 0ull, a1 = 0ull, b0 = 0ull, b1 = 0ull;
#pragma unroll
                for (int q = 0; q < 24; q += 2) {
                    a0 = fma2(h2[q],     w0[q],     a0);
                    a1 = fma2(h2[q + 1], w0[q + 1], a1);
                    b0 = fma2(h2[q],     w1[q],     b0);
                    b1 = fma2(h2[q + 1], w1[q + 1], b1);
                }
                a0 = fma2(h2[24], w0[24], a0);
                b0 = fma2(h2[24], w1[24], b0);
                a0 = add2(a0, a1);
                b0 = add2(b0, b1);
                const float2 sa = u2f(a0), sb = u2f(b0);
                d0 = xp0 + sa.x + sa.y;
                d1 = xp1 + sb.x + sb.y;
            }
            // p=0: si = sigm(i), tg = tanh(g) -> send si*tg
            // p=1: sf = sigm(f), so = sigm(o)
            float sendv = 0.f, sf = 0.f, so = 0.f;
            if (gatep) {
                if (p == 0) {
                    sendv = sigm(d0) * tanh_fast(d1);
                } else {
                    sf = sigm(d0);
                    so = sigm(d1);
                }
            }
            const float sitg = __shfl_xor_sync(0xffffffffu, sendv, 1);
            if (gatep && p == 1) {
                c = fmaf(sf, c, sitg);
                const float hn = so * tanh_fast(c);
                h_s[g][buf ^ 1][u] = hn;
                g_hs[(size_t)(t * B_ + b) * 50 + u] = hn;
            }
        }
        if (loader)
            asm volatile("cp.async.wait_group %0;" :: "n"(S_ - 3));
        asm volatile("bar.sync %0, 256;" :: "r"(g + 1) : "memory");
    }
}

// ---------------------------------------------------------------------------
// K3: head. out[r,:] = relu(h_r @ W1^T + b1) @ W2^T + b2 (flat over 51200 rows)
// ---------------------------------------------------------------------------
__global__ __launch_bounds__(256) void k3_head(
    const float* __restrict__ W1, const float* __restrict__ b1,
    const float* __restrict__ W2, const float* __restrict__ b2,
    float* __restrict__ out)
{
    __shared__ float sW1[16 * 50];
    __shared__ float sW2[9 * 16];
    __shared__ float sb1[16];
    __shared__ float sb2[9];

    const int tid = threadIdx.x;
    for (int i = tid; i < 800; i += 256) sW1[i] = W1[i];
    if (tid < 144) sW2[tid] = W2[tid];
    if (tid < 16)  sb1[tid] = b1[tid];
    if (tid < 9)   sb2[tid] = b2[tid];
    __syncthreads();

    const int r = blockIdx.x * 256 + tid;
    const float* __restrict__ hrow = &g_hs[(size_t)r * 50];

    float hv[50];
#pragma unroll
    for (int k = 0; k < 50; k++) hv[k] = hrow[k];

    float z[16];
#pragma unroll
    for (int jj = 0; jj < 16; jj++) {
        float a = sb1[jj];
#pragma unroll
        for (int k = 0; k < 50; k++) a = fmaf(hv[k], sW1[jj * 50 + k], a);
        z[jj] = fmaxf(a, 0.f);
    }
#pragma unroll
    for (int pp = 0; pp < 9; pp++) {
        float o = sb2[pp];
#pragma unroll
        for (int jj = 0; jj < 16; jj++) o = fmaf(z[jj], sW2[pp * 16 + jj], o);
        out[r * 9 + pp] = o;
    }
}

// ---------------------------------------------------------------------------
extern "C" void kernel_launch(void* const* d_in, const int* in_sizes, int n_in,
                              void* d_out, int out_size)
{
    const int*   tokens = (const int*)  d_in[0];
    const float* emb    = (const float*)d_in[1];
    const float* Wih    = (const float*)d_in[2];
    const float* Whh    = (const float*)d_in[3];
    const float* bih    = (const float*)d_in[4];
    const float* bhh    = (const float*)d_in[5];
    const float* W1     = (const float*)d_in[6];
    const float* b1     = (const float*)d_in[7];
    const float* W2     = (const float*)d_in[8];
    const float* b2     = (const float*)d_in[9];
    float* out = (float*)d_out;

    const int k1_smem = K1_SMEM_WORDS * 4;   // 168,736 B
    cudaFuncSetAttribute(k1_xproj, cudaFuncAttributeMaxDynamicSharedMemorySize,
                         k1_smem);

    k1_xproj<<<148, 512, k1_smem>>>(tokens, emb, Wih, bih, bhh);
    k2_lstm <<<B_ / 2, 512>>>(Whh);
    k3_head <<<M_ / 256, 256>>>(W1, b1, W2, b2, out);
}

// round 7
// speedup vs baseline: 1.4285x; 1.4285x over previous
#include <cuda_runtime.h>
#include <cuda_bf16.h>
#include <cmath>

#define T_  200
#define B_  256
#define M_  (T_ * B_)      // 51200 rows

__device__ float g_xproj[M_ * 200];  // [T,B,4H] flat row r = t*256+b
__device__ float g_hs[M_ * 50];      // [T,B,H]

// ---------------- helpers ----------------
__device__ __forceinline__ unsigned long long fma2(unsigned long long a,
                                                   unsigned long long b,
                                                   unsigned long long c) {
    unsigned long long d;
    asm("fma.rn.f32x2 %0, %1, %2, %3;" : "=l"(d) : "l"(a), "l"(b), "l"(c));
    return d;
}
__device__ __forceinline__ unsigned long long add2(unsigned long long a,
                                                   unsigned long long b) {
    unsigned long long d;
    asm("add.rn.f32x2 %0, %1, %2;" : "=l"(d) : "l"(a), "l"(b));
    return d;
}
__device__ __forceinline__ float2 u2f(unsigned long long v) {
    float2 r;
    asm("mov.b64 {%0, %1}, %2;" : "=f"(r.x), "=f"(r.y) : "l"(v));
    return r;
}
__device__ __forceinline__ unsigned smem_u32(const void* p) {
    return (unsigned)__cvta_generic_to_shared(p);
}
__device__ __forceinline__ void cp16(unsigned dst, const void* src) {
    asm volatile("cp.async.cg.shared.global [%0], [%1], 16;" :: "r"(dst), "l"(src));
}
__device__ __forceinline__ float frcp(float x) {
    float r; asm("rcp.approx.f32 %0, %1;" : "=f"(r) : "f"(x)); return r;
}
__device__ __forceinline__ float sigm(float x) {
    return frcp(1.f + __expf(-x));
}

__device__ __forceinline__ void mma_bf16(float* c, const unsigned* a,
                                         unsigned b0, unsigned b1) {
    asm volatile(
        "mma.sync.aligned.m16n8k16.row.col.f32.bf16.bf16.f32 "
        "{%0,%1,%2,%3}, {%4,%5,%6,%7}, {%8,%9}, {%0,%1,%2,%3};"
        : "+f"(c[0]), "+f"(c[1]), "+f"(c[2]), "+f"(c[3])
        : "r"(a[0]), "r"(a[1]), "r"(a[2]), "r"(a[3]), "r"(b0), "r"(b1));
}

// split x into bf16 hi/lo (hi = rn(x), lo = rn(x - hi))
__device__ __forceinline__ void bf16_split(float x, __nv_bfloat16& h,
                                           __nv_bfloat16& l) {
    h = __float2bfloat16_rn(x);
    l = __float2bfloat16_rn(x - __bfloat162float(h));
}
__device__ __forceinline__ unsigned pack_bf2(__nv_bfloat16 lo16, __nv_bfloat16 hi16) {
    __nv_bfloat162 v(lo16, hi16);   // .x = low half, .y = high half
    return *reinterpret_cast<unsigned*>(&v);
}

// ---------------------------------------------------------------------------
// K1 (tensor): x_proj = gather(emb, tokens) @ Wih^T + (bih+bhh)
// Persistent 148 CTAs x 256 threads. bf16 3-term split, mma.m16n8k16.
// Tile M=64 x N=200 (25 n-tiles), K=128 (8 k16-steps).
// Warps: wm = wid>>2 (m32 sub-tile), ng = wid&3 (n-group: 7/6/6/6 n-tiles).
// smem word layout:
//   BHI[12800]  : B-frag words, idx ((s*25+nt)*2+h)*32 + lane
//   BLO[12800]
//   AHI[64*68]  : A plane, word (row, kp) at row*68+kp (pad 68 -> conflict-free)
//   ALO[64*68]
//   ASTA[2][8192] : fp32 gather staging (double-buffered)
//   BSUM[200]
// ---------------------------------------------------------------------------
#define W_BHI  0
#define W_BLO  12800
#define W_AHI  25600
#define W_ALO  29952
#define W_ASTA 34304
#define W_BSUM 50688
#define K1_SMEM_WORDS 50888   // 203,552 bytes

__global__ __launch_bounds__(256, 1) void k1_mma(
    const int*   __restrict__ tokens,
    const float* __restrict__ emb,
    const float* __restrict__ Wih,
    const float* __restrict__ bih,
    const float* __restrict__ bhh)
{
    extern __shared__ __align__(16) float sm[];
    unsigned* BHI = reinterpret_cast<unsigned*>(sm + W_BHI);
    unsigned* BLO = reinterpret_cast<unsigned*>(sm + W_BLO);
    unsigned* AHI = reinterpret_cast<unsigned*>(sm + W_AHI);
    unsigned* ALO = reinterpret_cast<unsigned*>(sm + W_ALO);
    float*    ASTA = sm + W_ASTA;
    float*    bsum = sm + W_BSUM;

    const int tid  = threadIdx.x;
    const int lane = tid & 31;
    const int wid  = tid >> 5;
    const int wm   = wid >> 2;       // 0/1 : rows wm*32..wm*32+31
    const int ng   = wid & 3;        // n-group
    const int ntb  = (ng == 0) ? 0 : (ng == 1 ? 7 : (ng == 2 ? 13 : 19));
    const int ncnt = (ng == 0) ? 7 : 6;

    const int r_ln = lane >> 2;      // 0..7
    const int c_ln = lane & 3;       // 0..3

    const int cta   = blockIdx.x;
    const int nblk  = (cta < 60) ? 6 : 5;
    const int start = cta * 5 + ((cta < 60) ? cta : 60);

    if (tid < 200) bsum[tid] = bih[tid] + bhh[tid];

    // prologue: gather A tile 0 into staging buffer 0
    {
        const int row0 = start * 64;
        for (int i = tid; i < 2048; i += 256) {
            const int m  = i >> 5;
            const int ch = i & 31;
            cp16(smem_u32(&ASTA[m * 128 + ch * 4]),
                 emb + (size_t)tokens[row0 + m] * 128 + ch * 4);
        }
        asm volatile("cp.async.commit_group;");
    }

    // B conversion (once per CTA): Wih -> BHI/BLO frag layout
    for (int i = tid; i < 12800; i += 256) {
        const int n  = i >> 6;
        const int kp = i & 63;
        const int s  = kp >> 3;
        const int h  = (kp >> 2) & 1;
        const int cc = kp & 3;
        const int nt = n >> 3;
        const int gg = n & 7;
        const int dst = ((s * 25 + nt) * 2 + h) * 32 + gg * 4 + cc;
        const float2 v = *reinterpret_cast<const float2*>(Wih + n * 128 + 2 * kp);
        __nv_bfloat16 h0, l0, h1, l1;
        bf16_split(v.x, h0, l0);
        bf16_split(v.y, h1, l1);
        BHI[dst] = pack_bf2(h0, h1);
        BLO[dst] = pack_bf2(l0, l1);
    }

    for (int blk = 0; blk < nblk; blk++) {
        // (1) wait for A tile blk in staging buffer blk&1
        asm volatile("cp.async.wait_group 0;");
        __syncthreads();

        // (2) issue gather for tile blk+1 into the other buffer
        if (blk + 1 < nblk) {
            const int row0 = (start + blk + 1) * 64;
            float* dst = ASTA + ((blk + 1) & 1) * 8192;
            for (int i = tid; i < 2048; i += 256) {
                const int m  = i >> 5;
                const int ch = i & 31;
                cp16(smem_u32(&dst[m * 128 + ch * 4]),
                     emb + (size_t)tokens[row0 + m] * 128 + ch * 4);
            }
        }
        asm volatile("cp.async.commit_group;");

        // (3) convert A tile -> AHI/ALO planes
        {
            const float* src = ASTA + (blk & 1) * 8192 + (tid >> 2) * 128
                               + (tid & 3) * 32;
            const int wbase = (tid >> 2) * 68 + (tid & 3) * 16;
            unsigned hw[16], lw[16];
#pragma unroll
            for (int jj = 0; jj < 16; jj++) {
                const float x0 = src[2 * jj];
                const float x1 = src[2 * jj + 1];
                __nv_bfloat16 h0, l0, h1, l1;
                bf16_split(x0, h0, l0);
                bf16_split(x1, h1, l1);
                hw[jj] = pack_bf2(h0, h1);
                lw[jj] = pack_bf2(l0, l1);
            }
#pragma unroll
            for (int q4 = 0; q4 < 4; q4++) {
                *reinterpret_cast<uint4*>(&AHI[wbase + 4 * q4]) =
                    make_uint4(hw[4*q4], hw[4*q4+1], hw[4*q4+2], hw[4*q4+3]);
                *reinterpret_cast<uint4*>(&ALO[wbase + 4 * q4]) =
                    make_uint4(lw[4*q4], lw[4*q4+1], lw[4*q4+2], lw[4*q4+3]);
            }
        }
        __syncthreads();

        // (4) MMA phase
        float acc[7][2][4];
#pragma unroll
        for (int nt = 0; nt < 7; nt++)
#pragma unroll
            for (int f = 0; f < 2; f++)
#pragma unroll
                for (int e = 0; e < 4; e++) acc[nt][f][e] = 0.f;

#pragma unroll
        for (int s = 0; s < 8; s++) {
            unsigned ah[2][4], al[2][4];
#pragma unroll
            for (int f = 0; f < 2; f++) {
                const int row = wm * 32 + f * 16 + r_ln;
                const int base = row * 68 + s * 8 + c_ln;
                ah[f][0] = AHI[base];
                ah[f][1] = AHI[base + 8 * 68];
                ah[f][2] = AHI[base + 4];
                ah[f][3] = AHI[base + 8 * 68 + 4];
                al[f][0] = ALO[base];
                al[f][1] = ALO[base + 8 * 68];
                al[f][2] = ALO[base + 4];
                al[f][3] = ALO[base + 8 * 68 + 4];
            }
#pragma unroll
            for (int nt = 0; nt < 7; nt++) {
                if (nt < ncnt) {
                    const int bb = ((s * 25 + ntb + nt) * 2) * 32 + lane;
                    const unsigned bh0 = BHI[bb], bh1 = BHI[bb + 32];
                    const unsigned bl0 = BLO[bb], bl1 = BLO[bb + 32];
#pragma unroll
                    for (int f = 0; f < 2; f++) {
                        mma_bf16(acc[nt][f], ah[f], bh0, bh1);
                        mma_bf16(acc[nt][f], ah[f], bl0, bl1);
                        mma_bf16(acc[nt][f], al[f], bh0, bh1);
                    }
                }
            }
        }

        // epilogue: bias + store
        const int tile_row0 = (start + blk) * 64;
#pragma unroll
        for (int nt = 0; nt < 7; nt++) {
            if (nt < ncnt) {
                const int col = (ntb + nt) * 8 + 2 * c_ln;
                const float bx = bsum[col];
                const float by = bsum[col + 1];
#pragma unroll
                for (int f = 0; f < 2; f++) {
                    const int row = tile_row0 + wm * 32 + f * 16 + r_ln;
                    float2 o0, o1;
                    o0.x = acc[nt][f][0] + bx;
                    o0.y = acc[nt][f][1] + by;
                    o1.x = acc[nt][f][2] + bx;
                    o1.y = acc[nt][f][3] + by;
                    *reinterpret_cast<float2*>(
                        &g_xproj[(size_t)row * 200 + col]) = o0;
                    *reinterpret_cast<float2*>(
                        &g_xproj[(size_t)(row + 8) * 200 + col]) = o1;
                }
            }
        }
        // (5) planes free for next tile's convert
        __syncthreads();
    }
}

// ---------------------------------------------------------------------------
// K2: LSTM recurrence (R5 version: rotated SMSP roles, 8-deep cp.async ring)
// ---------------------------------------------------------------------------
#define S_ 8

__global__ __launch_bounds__(512, 1) void k2_lstm(const float* __restrict__ Whh)
{
    __shared__ __align__(16) float h_s[2][52];
    __shared__ float gates_s[2][200];
    __shared__ __align__(16) float xs[2][S_][200];

    const int tid = threadIdx.x;
    const int g   = tid >> 8;
    const int n   = tid & 255;
    const int v   = g ? ((n + 64) & 255) : n;   // rotated role index
    const int b   = blockIdx.x * 2 + g;

    const bool gate   = (v < 200);
    const bool loader = (v < 50);

    unsigned long long w2[25];
    if (gate) {
        const float2* wr = reinterpret_cast<const float2*>(Whh + v * 50);
#pragma unroll
        for (int q = 0; q < 25; q++)
            w2[q] = *reinterpret_cast<const unsigned long long*>(&wr[q]);
    }
    if (v < 52) h_s[g][v] = 0.f;

    if (loader) {
#pragma unroll
        for (int s = 0; s < S_ - 1; s++) {
            cp16(smem_u32(&xs[g][s][v * 4]),
                 g_xproj + ((size_t)(s * B_ + b) * 200) + v * 4);
            asm volatile("cp.async.commit_group;");
        }
        asm volatile("cp.async.wait_group %0;" :: "n"(S_ - 3));
    }
    __syncthreads();

    float c = 0.f;

    for (int t = 0; t < T_; t++) {
        const int slot = t & (S_ - 1);

        if (loader) {
            const int ts = t + S_ - 1;
            if (ts < T_)
                cp16(smem_u32(&xs[g][ts & (S_ - 1)][v * 4]),
                     g_xproj + ((size_t)(ts * B_ + b) * 200) + v * 4);
            asm volatile("cp.async.commit_group;");
        }

        if (gate) {
            const float xp = xs[g][slot][v];
            const unsigned long long* h2 =
                reinterpret_cast<const unsigned long long*>(h_s[g]);
            unsigned long long a0 = 0ull, a1 = 0ull, a2 = 0ull, a3 = 0ull;
#pragma unroll
            for (int q = 0; q < 24; q += 4) {
                a0 = fma2(h2[q],     w2[q],     a0);
                a1 = fma2(h2[q + 1], w2[q + 1], a1);
                a2 = fma2(h2[q + 2], w2[q + 2], a2);
                a3 = fma2(h2[q + 3], w2[q + 3], a3);
            }
            a0 = fma2(h2[24], w2[24], a0);
            a0 = add2(a0, a1);
            a2 = add2(a2, a3);
            a0 = add2(a0, a2);
            const float2 s = u2f(a0);
            gates_s[g][v] = xp + s.x + s.y;
        }
        if (loader)
            asm volatile("cp.async.wait_group %0;" :: "n"(S_ - 3));
        asm volatile("bar.sync %0, 256;" :: "r"(g + 1) : "memory");

        if (v < 50) {
            const float iv = gates_s[g][v];
            const float fv = gates_s[g][v + 50];
            const float gv = gates_s[g][v + 100];
            const float ov = gates_s[g][v + 150];
            const float si = sigm(iv);
            const float sf = sigm(fv);
            const float so = sigm(ov);
            const float tg = fmaf(2.f, sigm(2.f * gv), -1.f);
            c = fmaf(sf, c, si * tg);
            const float tc = fmaf(2.f, sigm(2.f * c), -1.f);
            const float hn = so * tc;
            h_s[g][v] = hn;
            g_hs[(size_t)(t * B_ + b) * 50 + v] = hn;
        }
        asm volatile("bar.sync %0, 256;" :: "r"(g + 1) : "memory");
    }
}

// ---------------------------------------------------------------------------
// K3: head. out[r,:] = relu(h_r @ W1^T + b1) @ W2^T + b2 (flat 51200 rows)
// ---------------------------------------------------------------------------
__global__ __launch_bounds__(256) void k3_head(
    const float* __restrict__ W1, const float* __restrict__ b1,
    const float* __restrict__ W2, const float* __restrict__ b2,
    float* __restrict__ out)
{
    __shared__ float sW1[16 * 50];
    __shared__ float sW2[9 * 16];
    __shared__ float sb1[16];
    __shared__ float sb2[9];

    const int tid = threadIdx.x;
    for (int i = tid; i < 800; i += 256) sW1[i] = W1[i];
    if (tid < 144) sW2[tid] = W2[tid];
    if (tid < 16)  sb1[tid] = b1[tid];
    if (tid < 9)   sb2[tid] = b2[tid];
    __syncthreads();

    const int r = blockIdx.x * 256 + tid;
    const float* __restrict__ hrow = &g_hs[(size_t)r * 50];

    float hv[50];
#pragma unroll
    for (int k = 0; k < 50; k++) hv[k] = hrow[k];

    float z[16];
#pragma unroll
    for (int jj = 0; jj < 16; jj++) {
        float a = sb1[jj];
#pragma unroll
        for (int k = 0; k < 50; k++) a = fmaf(hv[k], sW1[jj * 50 + k], a);
        z[jj] = fmaxf(a, 0.f);
    }
#pragma unroll
    for (int pp = 0; pp < 9; pp++) {
        float o = sb2[pp];
#pragma unroll
        for (int jj = 0; jj < 16; jj++) o = fmaf(z[jj], sW2[pp * 16 + jj], o);
        out[r * 9 + pp] = o;
    }
}

// ---------------------------------------------------------------------------
extern "C" void kernel_launch(void* const* d_in, const int* in_sizes, int n_in,
                              void* d_out, int out_size)
{
    const int*   tokens = (const int*)  d_in[0];
    const float* emb    = (const float*)d_in[1];
    const float* Wih    = (const float*)d_in[2];
    const float* Whh    = (const float*)d_in[3];
    const float* bih    = (const float*)d_in[4];
    const float* bhh    = (const float*)d_in[5];
    const float* W1     = (const float*)d_in[6];
    const float* b1     = (const float*)d_in[7];
    const float* W2     = (const float*)d_in[8];
    const float* b2     = (const float*)d_in[9];
    float* out = (float*)d_out;

    const int k1_smem = K1_SMEM_WORDS * 4;   // 203,552 B
    cudaFuncSetAttribute(k1_mma, cudaFuncAttributeMaxDynamicSharedMemorySize,
                         k1_smem);

    k1_mma  <<<148, 256, k1_smem>>>(tokens, emb, Wih, bih, bhh);
    k2_lstm <<<B_ / 2, 512>>>(Whh);
    k3_head <<<M_ / 256, 256>>>(W1, b1, W2, b2, out);
}